// round 1
// baseline (speedup 1.0000x reference)
#include <cuda_runtime.h>
#include <math.h>

#define HID   768
#define INTER 1536
#define DK    128
#define NCOL  (2*INTER + DK)   // 3200
#define BATCH 4
#define SEQ   2048
#define MTOT  (BATCH*SEQ)      // 8192

// -------- scratch (no allocations allowed) --------
__device__ float g_x  [(size_t)MTOT * NCOL];    // silu(H@Wi)        104.8 MB
__device__ float g_qkw[(size_t)MTOT * DK];      // qk * (qg*kg)        4.2 MB
__device__ float g_A  [(size_t)BATCH*SEQ*SEQ];  // attention matrix   67.1 MB
__device__ float g_pv [(size_t)MTOT * INTER];   // u * (A@v)          50.3 MB
__device__ float g_scale[BATCH];

// -------- tiling --------
#define BM 128
#define BN 128
#define BK 8
#define TM 8
#define TN 8
// 256 threads: 16x16 thread grid, each thread owns an 8x8 micro-tile

// ---------------------------------------------------------------------------
// per-batch mask sum -> combined logit scale log(l)/(LOG512*sqrt(DK))
// ---------------------------------------------------------------------------
__global__ void compute_scale_k(const int* __restrict__ mask)
{
    int b = blockIdx.x, t = threadIdx.x;
    int s = 0;
    for (int i = t; i < SEQ; i += 256) s += mask[(long)b*SEQ + i];
#pragma unroll
    for (int o = 16; o > 0; o >>= 1) s += __shfl_xor_sync(0xffffffffu, s, o);
    __shared__ int red[8];
    if ((t & 31) == 0) red[t >> 5] = s;
    __syncthreads();
    if (t == 0) {
        int tot = 0;
#pragma unroll
        for (int i = 0; i < 8; i++) tot += red[i];
        // LOG512 = ln(512), sqrt(128)
        g_scale[b] = logf((float)tot) / (6.2383246250395075f * 11.313708498984761f);
    }
}

// ---------------------------------------------------------------------------
// qkw[r,d] = x[r, 2*INTER+d] * q_gamma[d] * k_gamma[d]
// ---------------------------------------------------------------------------
__global__ void make_qkw_k(const float* __restrict__ x,
                           const float* __restrict__ qg,
                           const float* __restrict__ kg,
                           float* __restrict__ qkw)
{
    long idx = (long)blockIdx.x * 256 + threadIdx.x;   // MTOT*DK total
    int  d   = (int)(idx & (DK - 1));
    long r   = idx >> 7;
    qkw[idx] = x[r * NCOL + 2*INTER + d] * qg[d] * kg[d];
}

// ---------------------------------------------------------------------------
// Generic NN SGEMM: C[M,N] = A[M,K] @ B[K,N], all row-major, dims multiples
// of tile sizes. mode: 0 plain, 1 silu, 2 multiply-by-gate G (same shape as C)
// Batched via blockIdx.z with element strides sA/sB/sC/sG.
// ---------------------------------------------------------------------------
__global__ __launch_bounds__(256) void sgemm_nn(
    const float* __restrict__ A, int lda, long sA,
    const float* __restrict__ Bm, int ldb, long sB,
    float* __restrict__ C, int ldc, long sC,
    const float* __restrict__ G, int ldg, long sG,
    int K, int mode)
{
    int bz = blockIdx.z;
    A  += (long)bz * sA;
    Bm += (long)bz * sB;
    C  += (long)bz * sC;
    if (mode == 2) G += (long)bz * sG;

    __shared__ float As[BK][BM + 4];
    __shared__ float Bs[BK][BN + 4];

    int tid  = threadIdx.x;
    long brow = (long)blockIdx.y * BM;
    long bcol = (long)blockIdx.x * BN;
    int tr = (tid >> 4) * TM;
    int tc = (tid & 15) * TN;

    float acc[TM][TN] = {};

    // A tile load: thread -> (row am, 4 k's), 256 threads cover 128x8
    int am = tid >> 1, ak = (tid & 1) * 4;
    // B tile load: thread -> (row bk, 4 n's), 256 threads cover 8x128
    int bk = tid >> 5, bn = (tid & 31) * 4;

    const float* Ag = A  + (brow + am) * (long)lda + ak;
    const float* Bg = Bm + (long)bk * ldb + bcol + bn;

    for (int k0 = 0; k0 < K; k0 += BK) {
        float4 av = *(const float4*)(Ag + k0);
        float4 bv = *(const float4*)(Bg + (long)k0 * ldb);
        As[ak+0][am] = av.x; As[ak+1][am] = av.y;
        As[ak+2][am] = av.z; As[ak+3][am] = av.w;
        *(float4*)&Bs[bk][bn] = bv;
        __syncthreads();
#pragma unroll
        for (int k = 0; k < BK; k++) {
            float ar[TM], br[TN];
#pragma unroll
            for (int i = 0; i < TM; i++) ar[i] = As[k][tr + i];
#pragma unroll
            for (int j = 0; j < TN; j++) br[j] = Bs[k][tc + j];
#pragma unroll
            for (int i = 0; i < TM; i++)
#pragma unroll
                for (int j = 0; j < TN; j++)
                    acc[i][j] += ar[i] * br[j];
        }
        __syncthreads();
    }

#pragma unroll
    for (int i = 0; i < TM; i++) {
        long r = brow + tr + i;
#pragma unroll
        for (int j = 0; j < TN; j++) {
            long c = bcol + tc + j;
            float v = acc[i][j];
            if (mode == 1)      v = v / (1.0f + expf(-v));        // silu
            else if (mode == 2) v *= G[r * (long)ldg + c];        // u-gate
            C[r * (long)ldc + c] = v;
        }
    }
}

// ---------------------------------------------------------------------------
// Scores (NT): C[m,n] = (qkw[m,:] . qk[n,:]) * scale, masked -> -1e30
// A = g_qkw (ld DK), B = g_x + 2*INTER (ld NCOL), per-batch via blockIdx.z
// ---------------------------------------------------------------------------
__global__ __launch_bounds__(256) void sgemm_scores(
    const float* __restrict__ Aq, const float* __restrict__ Bq,
    const int* __restrict__ mask, float* __restrict__ Cout)
{
    int bz = blockIdx.z;
    const float* A  = Aq + (long)bz * SEQ * DK;
    const float* Bm = Bq + (long)bz * SEQ * NCOL;
    float*       Cc = Cout + (long)bz * SEQ * SEQ;
    const int*   mk = mask + (long)bz * SEQ;

    __shared__ float As[BK][BM + 4];
    __shared__ float Bs[BK][BN + 4];

    int tid = threadIdx.x;
    int brow = blockIdx.y * BM;
    int bcol = blockIdx.x * BN;
    int tr = (tid >> 4) * TM;
    int tc = (tid & 15) * TN;

    float acc[TM][TN] = {};

    int am = tid >> 1, ak = (tid & 1) * 4;
    const float* Ag = A  + (long)(brow + am) * DK + ak;
    const float* Bg = Bm + (long)(bcol + am) * NCOL + ak;

    for (int k0 = 0; k0 < DK; k0 += BK) {
        float4 av = *(const float4*)(Ag + k0);
        float4 bv = *(const float4*)(Bg + k0);
        As[ak+0][am] = av.x; As[ak+1][am] = av.y;
        As[ak+2][am] = av.z; As[ak+3][am] = av.w;
        Bs[ak+0][am] = bv.x; Bs[ak+1][am] = bv.y;
        Bs[ak+2][am] = bv.z; Bs[ak+3][am] = bv.w;
        __syncthreads();
#pragma unroll
        for (int k = 0; k < BK; k++) {
            float ar[TM], br[TN];
#pragma unroll
            for (int i = 0; i < TM; i++) ar[i] = As[k][tr + i];
#pragma unroll
            for (int j = 0; j < TN; j++) br[j] = Bs[k][tc + j];
#pragma unroll
            for (int i = 0; i < TM; i++)
#pragma unroll
                for (int j = 0; j < TN; j++)
                    acc[i][j] += ar[i] * br[j];
        }
        __syncthreads();
    }

    float sc = g_scale[bz];
#pragma unroll
    for (int i = 0; i < TM; i++) {
        long r = brow + tr + i;
#pragma unroll
        for (int j = 0; j < TN; j++) {
            int c = bcol + tc + j;
            float v = acc[i][j] * sc;
            if (mk[c] == 0) v = -1e30f;
            Cc[r * (long)SEQ + c] = v;
        }
    }
}

// ---------------------------------------------------------------------------
// Row softmax over SEQ=2048 elements: 1 block (256 thr) per row, 8 vals/thread
// ---------------------------------------------------------------------------
__global__ __launch_bounds__(256) void softmax_rows(float* __restrict__ Am)
{
    float* p = Am + (long)blockIdx.x * SEQ;
    int t = threadIdx.x;
    float v[8];
    float mx = -3.4e38f;
#pragma unroll
    for (int i = 0; i < 8; i++) { v[i] = p[t + (i << 8)]; mx = fmaxf(mx, v[i]); }

    __shared__ float smax[8], ssum[8];
#pragma unroll
    for (int o = 16; o > 0; o >>= 1) mx = fmaxf(mx, __shfl_xor_sync(0xffffffffu, mx, o));
    if ((t & 31) == 0) smax[t >> 5] = mx;
    __syncthreads();
    if (t < 32) {
        float m = (t < 8) ? smax[t] : -3.4e38f;
#pragma unroll
        for (int o = 4; o > 0; o >>= 1) m = fmaxf(m, __shfl_xor_sync(0xffffffffu, m, o));
        if (t == 0) smax[0] = m;
    }
    __syncthreads();
    mx = smax[0];

    float s = 0.f;
#pragma unroll
    for (int i = 0; i < 8; i++) { v[i] = expf(v[i] - mx); s += v[i]; }
#pragma unroll
    for (int o = 16; o > 0; o >>= 1) s += __shfl_xor_sync(0xffffffffu, s, o);
    if ((t & 31) == 0) ssum[t >> 5] = s;
    __syncthreads();
    if (t < 32) {
        float m = (t < 8) ? ssum[t] : 0.f;
#pragma unroll
        for (int o = 4; o > 0; o >>= 1) m += __shfl_xor_sync(0xffffffffu, m, o);
        if (t == 0) ssum[0] = m;
    }
    __syncthreads();
    float inv = 1.0f / ssum[0];
#pragma unroll
    for (int i = 0; i < 8; i++) p[t + (i << 8)] = v[i] * inv;
}

// ---------------------------------------------------------------------------
extern "C" void kernel_launch(void* const* d_in, const int* in_sizes, int n_in,
                              void* d_out, int out_size)
{
    (void)in_sizes; (void)n_in; (void)out_size;
    const float* hidden = (const float*)d_in[0];
    const float* Wi     = (const float*)d_in[1];
    const float* Wo     = (const float*)d_in[2];
    const float* qg     = (const float*)d_in[3];
    const float* kg     = (const float*)d_in[4];
    const int*   mask   = (const int*)  d_in[5];
    float* out = (float*)d_out;

    float *px, *pqkw, *pA, *ppv;
    cudaGetSymbolAddress((void**)&px,   g_x);
    cudaGetSymbolAddress((void**)&pqkw, g_qkw);
    cudaGetSymbolAddress((void**)&pA,   g_A);
    cudaGetSymbolAddress((void**)&ppv,  g_pv);

    // 1) per-batch mask sum -> logit scale
    compute_scale_k<<<BATCH, 256>>>(mask);

    // 2) x = silu(H @ Wi)   [8192 x 3200]
    sgemm_nn<<<dim3(NCOL/BN, MTOT/BM, 1), 256>>>(
        hidden, HID, 0, Wi, NCOL, 0, px, NCOL, 0,
        nullptr, 0, 0, HID, /*silu*/1);

    // 3) qkw = qk * (q_gamma * k_gamma)
    make_qkw_k<<<(MTOT*DK)/256, 256>>>(px, qg, kg, pqkw);

    // 4) scores + mask + scale   [4 x 2048 x 2048]
    sgemm_scores<<<dim3(SEQ/BN, SEQ/BM, BATCH), 256>>>(pqkw, px + 2*INTER, mask, pA);

    // 5) row softmax
    softmax_rows<<<MTOT, 256>>>(pA);

    // 6) pv = u * (A @ v)   [8192 x 1536]
    sgemm_nn<<<dim3(INTER/BN, SEQ/BM, BATCH), 256>>>(
        pA, SEQ, (long)SEQ*SEQ,
        px + INTER, NCOL, (long)SEQ*NCOL,
        ppv, INTER, (long)SEQ*INTER,
        px, NCOL, (long)SEQ*NCOL,   // gate = u (cols 0..1535 of x)
        SEQ, /*gate*/2);

    // 7) out = pv @ Wo   [8192 x 768]
    sgemm_nn<<<dim3(HID/BN, MTOT/BM, 1), 256>>>(
        ppv, INTER, 0, Wo, HID, 0, out, HID, 0,
        nullptr, 0, 0, INTER, /*plain*/0);
}

// round 9
// speedup vs baseline: 2.2985x; 2.2985x over previous
#include <cuda_runtime.h>
#include <cuda_bf16.h>
#include <stdint.h>
#include <math.h>

#define HID   768
#define INTER 1536
#define DK    128
#define NCOL  3200
#define BATCH 4
#define SEQ   2048
#define MTOT  8192

#define KE1 (3*HID)
#define KES (3*DK)
#define KEA (3*SEQ)
#define KEO (3*INTER)

__device__ float g_x [(size_t)MTOT * NCOL];
__device__ float g_A [(size_t)BATCH * SEQ * SEQ];
__device__ float g_scale[BATCH];
__device__ __nv_bfloat16 g_Hext [(size_t)MTOT * KE1];
__device__ __nv_bfloat16 g_Wiext[(size_t)KE1 * NCOL];
__device__ __nv_bfloat16 g_qwext[(size_t)MTOT * KES];
__device__ __nv_bfloat16 g_qkT  [(size_t)BATCH * KES * SEQ];
__device__ __nv_bfloat16 g_Pext [(size_t)BATCH * SEQ * KEA];
__device__ __nv_bfloat16 g_vext [(size_t)BATCH * KEA * INTER];
__device__ __nv_bfloat16 g_pvext[(size_t)MTOT * KEO];
__device__ __nv_bfloat16 g_Woext[(size_t)KEO * HID];

__device__ __forceinline__ void bsplit(float v, __nv_bfloat16& h, __nv_bfloat16& l) {
    h = __float2bfloat16(v);
    l = __float2bfloat16(v - __bfloat162float(h));
}
__device__ __forceinline__ uint32_t smem_u32(const void* p) {
    uint32_t a;
    asm("{ .reg .u64 t; cvta.to.shared.u64 t, %1; cvt.u32.u64 %0, t; }" : "=r"(a) : "l"(p));
    return a;
}
#define LDMX4(r0,r1,r2,r3,addr) \
    asm volatile("ldmatrix.sync.aligned.m8n8.x4.shared.b16 {%0,%1,%2,%3}, [%4];" \
        : "=r"(r0),"=r"(r1),"=r"(r2),"=r"(r3) : "r"(addr))
#define LDMT4(r0,r1,r2,r3,addr) \
    asm volatile("ldmatrix.sync.aligned.m8n8.x4.trans.shared.b16 {%0,%1,%2,%3}, [%4];" \
        : "=r"(r0),"=r"(r1),"=r"(r2),"=r"(r3) : "r"(addr))
#define MMA16816(d, a, b0, b1) \
    asm volatile("mma.sync.aligned.m16n8k16.row.col.f32.bf16.bf16.f32 " \
        "{%0,%1,%2,%3},{%4,%5,%6,%7},{%8,%9},{%0,%1,%2,%3};" \
        : "+f"((d)[0]),"+f"((d)[1]),"+f"((d)[2]),"+f"((d)[3]) \
        : "r"((a)[0]),"r"((a)[1]),"r"((a)[2]),"r"((a)[3]),"r"(b0),"r"(b1))

__global__ void compute_scale_k(const int* __restrict__ mask)
{
    int b = blockIdx.x, t = threadIdx.x;
    int s = 0;
    for (int i = t; i < SEQ; i += 256) s += mask[(long)b*SEQ + i];
#pragma unroll
    for (int o = 16; o > 0; o >>= 1) s += __shfl_xor_sync(0xffffffffu, s, o);
    __shared__ int red[8];
    if ((t & 31) == 0) red[t >> 5] = s;
    __syncthreads();
    if (t == 0) {
        int tot = 0;
#pragma unroll
        for (int i = 0; i < 8; i++) tot += red[i];
        g_scale[b] = logf((float)tot) / (6.2383246250395075f * 11.313708498984761f);
    }
}

__global__ void conv_H(const float* __restrict__ Hs)
{
    long idx = (long)blockIdx.x * 256 + threadIdx.x;
    long r = idx / HID; int c = (int)(idx % HID);
    __nv_bfloat16 h, l; bsplit(Hs[idx], h, l);
    __nv_bfloat16* p = g_Hext + r * KE1 + c;
    p[0] = h; p[HID] = h; p[2*HID] = l;
}

__global__ void conv_Wi(const float* __restrict__ Wi)
{
    long idx = (long)blockIdx.x * 256 + threadIdx.x;
    long r = idx / NCOL; int c = (int)(idx % NCOL);
    __nv_bfloat16 h, l; bsplit(Wi[idx], h, l);
    g_Wiext[ r          * (long)NCOL + c] = h;
    g_Wiext[(r +   HID) * (long)NCOL + c] = l;
    g_Wiext[(r + 2*HID) * (long)NCOL + c] = h;
}

__global__ void conv_Wo(const float* __restrict__ Wo)
{
    long idx = (long)blockIdx.x * 256 + threadIdx.x;
    long r = idx / HID; int c = (int)(idx % HID);
    __nv_bfloat16 h, l; bsplit(Wo[idx], h, l);
    g_Woext[ r            * (long)HID + c] = h;
    g_Woext[(r +   INTER) * (long)HID + c] = l;
    g_Woext[(r + 2*INTER) * (long)HID + c] = h;
}

__global__ void conv_qk(const float* __restrict__ qg, const float* __restrict__ kg)
{
    long idx = (long)blockIdx.x * 256 + threadIdx.x;
    long gr = idx >> 7; int d = (int)(idx & (DK - 1));
    float xv = g_x[gr * NCOL + 2*INTER + d];
    __nv_bfloat16 h, l;
    bsplit(xv * qg[d] * kg[d], h, l);
    __nv_bfloat16* p = g_qwext + gr * KES + d;
    p[0] = h; p[DK] = h; p[2*DK] = l;
    bsplit(xv, h, l);
    long b = gr >> 11, n = gr & (SEQ - 1);
    __nv_bfloat16* q = g_qkT + b * (long)KES * SEQ + n;
    q[(long)d * SEQ]          = h;
    q[(long)(DK + d) * SEQ]   = l;
    q[(long)(2*DK + d) * SEQ] = h;
}

__global__ void conv_v(int dummy)
{
    long idx = (long)blockIdx.x * 256 + threadIdx.x;
    long gr = idx / INTER; int j = (int)(idx % INTER);
    float xv = g_x[gr * NCOL + INTER + j];
    __nv_bfloat16 h, l; bsplit(xv, h, l);
    long b = gr >> 11, n = gr & (SEQ - 1);
    __nv_bfloat16* p = g_vext + b * (long)KEA * INTER + j;
    p[ n          * (long)INTER] = h;
    p[(n +   SEQ) * (long)INTER] = l;
    p[(n + 2*SEQ) * (long)INTER] = h;
}

__global__ __launch_bounds__(256) void softmax_rows(int dummy)
{
    long gr = blockIdx.x;
    const float* p = g_A + gr * SEQ;
    long b = gr >> 11, m = gr & (SEQ - 1);
    __nv_bfloat16* pe = g_Pext + b * (long)SEQ * KEA + m * (long)KEA;

    int t = threadIdx.x;
    float v[8];
    float mx = -3.4e38f;
#pragma unroll
    for (int i = 0; i < 8; i++) { v[i] = p[t + (i << 8)]; mx = fmaxf(mx, v[i]); }
    __shared__ float smax[8], ssum[8];
#pragma unroll
    for (int o = 16; o > 0; o >>= 1) mx = fmaxf(mx, __shfl_xor_sync(0xffffffffu, mx, o));
    if ((t & 31) == 0) smax[t >> 5] = mx;
    __syncthreads();
    if (t < 32) {
        float m2 = (t < 8) ? smax[t] : -3.4e38f;
#pragma unroll
        for (int o = 4; o > 0; o >>= 1) m2 = fmaxf(m2, __shfl_xor_sync(0xffffffffu, m2, o));
        if (t == 0) smax[0] = m2;
    }
    __syncthreads();
    mx = smax[0];
    float s = 0.f;
#pragma unroll
    for (int i = 0; i < 8; i++) { v[i] = expf(v[i] - mx); s += v[i]; }
#pragma unroll
    for (int o = 16; o > 0; o >>= 1) s += __shfl_xor_sync(0xffffffffu, s, o);
    if ((t & 31) == 0) ssum[t >> 5] = s;
    __syncthreads();
    if (t < 32) {
        float m2 = (t < 8) ? ssum[t] : 0.f;
#pragma unroll
        for (int o = 4; o > 0; o >>= 1) m2 += __shfl_xor_sync(0xffffffffu, m2, o);
        if (t == 0) ssum[0] = m2;
    }
    __syncthreads();
    float inv = 1.0f / ssum[0];
#pragma unroll
    for (int i = 0; i < 8; i++) {
        int n = t + (i << 8);
        __nv_bfloat16 h, l; bsplit(v[i] * inv, h, l);
        pe[n] = h; pe[SEQ + n] = h; pe[2*SEQ + n] = l;
    }
}

template<int MODE>
__global__ __launch_bounds__(256) void bmma_gemm(
    const __nv_bfloat16* __restrict__ A, int lda, long sA,
    const __nv_bfloat16* __restrict__ B, int ldb, long sB,
    float* __restrict__ Cf, int ldc, long sC,
    __nv_bfloat16* __restrict__ Cb, long sCb,
    const float* __restrict__ U, long sU,
    const int* __restrict__ maskb,
    int K)
{
    const int bz = blockIdx.z;
    A += (long)bz * sA;
    B += (long)bz * sB;
    const int* mk = (MODE == 2) ? (maskb + (long)bz * SEQ) : nullptr;

    __shared__ __align__(16) __nv_bfloat16 As[128][40];
    __shared__ __align__(16) __nv_bfloat16 Bs[32][136];

    const int tid  = threadIdx.x;
    const int lane = tid & 31;
    const int wid  = tid >> 5;
    const int warp_m = wid >> 1;
    const int warp_n = wid & 1;
    const int brow = blockIdx.y * 128;
    const int bcol = blockIdx.x * 128;

    const int aRow = tid >> 2,  aCol = (tid & 3) * 8;
    const int bRow = tid >> 4,  bCol = (tid & 15) * 8;

    const __nv_bfloat16* Ag0 = A + (long)(brow + aRow)      * lda + aCol;
    const __nv_bfloat16* Ag1 = A + (long)(brow + aRow + 64) * lda + aCol;
    const __nv_bfloat16* Bg0 = B + (long)bRow        * ldb + bcol + bCol;
    const __nv_bfloat16* Bg1 = B + (long)(bRow + 16) * ldb + bcol + bCol;

    const uint32_t asBase = smem_u32(&As[0][0]);
    const uint32_t bsBase = smem_u32(&Bs[0][0]);
    const int aLmRow = warp_m * 32 + ((lane >> 3) & 1) * 8 + (lane & 7);
    const int aLmCol = (lane >> 4) * 8;
    const int bLmRow = ((lane >> 3) & 1) * 8 + (lane & 7);
    const int bLmCol = warp_n * 64 + (lane >> 4) * 8;

    float acc[2][8][4] = {};

    const int nK = K / 32;
    int4 ra0 = *(const int4*)Ag0;
    int4 ra1 = *(const int4*)Ag1;
    int4 rb0 = *(const int4*)Bg0;
    int4 rb1 = *(const int4*)Bg1;

    for (int kc = 0; kc < nK; kc++) {
        *(int4*)&As[aRow][aCol]      = ra0;
        *(int4*)&As[aRow + 64][aCol] = ra1;
        *(int4*)&Bs[bRow][bCol]      = rb0;
        *(int4*)&Bs[bRow + 16][bCol] = rb1;
        __syncthreads();

        if (kc + 1 < nK) {
            int ko = (kc + 1) * 32;
            ra0 = *(const int4*)(Ag0 + ko);
            ra1 = *(const int4*)(Ag1 + ko);
            rb0 = *(const int4*)(Bg0 + (long)ko * ldb);
            rb1 = *(const int4*)(Bg1 + (long)ko * ldb);
        }

#pragma unroll
        for (int kk = 0; kk < 2; kk++) {
            uint32_t a[2][4];
#pragma unroll
            for (int mf = 0; mf < 2; mf++) {
                uint32_t addr = asBase + (uint32_t)(((aLmRow + mf*16) * 40 + aLmCol + kk*16) * 2);
                LDMX4(a[mf][0], a[mf][1], a[mf][2], a[mf][3], addr);
            }
            uint32_t b[4][4];
#pragma unroll
            for (int p = 0; p < 4; p++) {
                uint32_t addr = bsBase + (uint32_t)(((bLmRow + kk*16) * 136 + bLmCol + p*16) * 2);
                LDMT4(b[p][0], b[p][1], b[p][2], b[p][3], addr);
            }
#pragma unroll
            for (int mf = 0; mf < 2; mf++)
#pragma unroll
                for (int nf = 0; nf < 8; nf++)
                    MMA16816(acc[mf][nf], a[mf], b[nf >> 1][(nf & 1) * 2], b[nf >> 1][(nf & 1) * 2 + 1]);
        }
        __syncthreads();
    }

    const int lr = lane >> 2, lc = (lane & 3) * 2;
    float scl = (MODE == 2) ? g_scale[bz] : 0.f;

#pragma unroll
    for (int mf = 0; mf < 2; mf++) {
#pragma unroll
        for (int i = 0; i < 2; i++) {
            int row = brow + warp_m * 32 + mf * 16 + i * 8 + lr;
#pragma unroll
            for (int nf = 0; nf < 8; nf++) {
                int col = bcol + warp_n * 64 + nf * 8 + lc;
                float v0 = acc[mf][nf][i * 2 + 0];
                float v1 = acc[mf][nf][i * 2 + 1];
                if (MODE == 0) {
                    float* c = Cf + (long)bz * sC + (long)row * ldc + col;
                    c[0] = v0; c[1] = v1;
                } else if (MODE == 1) {
                    v0 = v0 / (1.0f + expf(-v0));
                    v1 = v1 / (1.0f + expf(-v1));
                    float* c = Cf + (long)bz * sC + (long)row * ldc + col;
                    c[0] = v0; c[1] = v1;
                } else if (MODE == 2) {
                    v0 *= scl; v1 *= scl;
                    if (mk[col]     == 0) v0 = -1e30f;
                    if (mk[col + 1] == 0) v1 = -1e30f;
                    float* c = Cf + (long)bz * sC + (long)row * ldc + col;
                    c[0] = v0; c[1] = v1;
                } else {
                    const float* u = U + (long)bz * sU + (long)row * NCOL + col;
                    v0 *= u[0]; v1 *= u[1];
                    __nv_bfloat16 h0, l0, h1, l1;
                    bsplit(v0, h0, l0); bsplit(v1, h1, l1);
                    __nv_bfloat16* c = Cb + (long)bz * sCb + (long)row * KEO + col;
                    *(__nv_bfloat162*)(c)           = __halves2bfloat162(h0, h1);
                    *(__nv_bfloat162*)(c + INTER)   = __halves2bfloat162(h0, h1);
                    *(__nv_bfloat162*)(c + 2*INTER) = __halves2bfloat162(l0, l1);
                }
            }
        }
    }
}

extern "C" void kernel_launch(void* const* d_in, const int* in_sizes, int n_in,
                              void* d_out, int out_size)
{
    (void)in_sizes; (void)n_in; (void)out_size;
    const float* hidden = (const float*)d_in[0];
    const float* Wi     = (const float*)d_in[1];
    const float* Wo     = (const float*)d_in[2];
    const float* qg     = (const float*)d_in[3];
    const float* kg     = (const float*)d_in[4];
    const int*   mask   = (const int*)  d_in[5];
    float* out = (float*)d_out;

    float *px, *pA;
    __nv_bfloat16 *pH, *pWi, *pqw, *pqkT, *pP, *pv, *ppv, *pWo;
    cudaGetSymbolAddress((void**)&px,  g_x);
    cudaGetSymbolAddress((void**)&pA,  g_A);
    cudaGetSymbolAddress((void**)&pH,  g_Hext);
    cudaGetSymbolAddress((void**)&pWi, g_Wiext);
    cudaGetSymbolAddress((void**)&pqw, g_qwext);
    cudaGetSymbolAddress((void**)&pqkT,g_qkT);
    cudaGetSymbolAddress((void**)&pP,  g_Pext);
    cudaGetSymbolAddress((void**)&pv,  g_vext);
    cudaGetSymbolAddress((void**)&ppv, g_pvext);
    cudaGetSymbolAddress((void**)&pWo, g_Woext);

    compute_scale_k<<<BATCH, 256>>>(mask);
    conv_H <<<(MTOT*HID)/256, 256>>>(hidden);
    conv_Wi<<<(HID*NCOL)/256, 256>>>(Wi);
    conv_Wo<<<(INTER*HID)/256, 256>>>(Wo);

    bmma_gemm<1><<<dim3(NCOL/128, MTOT/128, 1), 256>>>(
        pH, KE1, 0, pWi, NCOL, 0, px, NCOL, 0,
        nullptr, 0, nullptr, 0, nullptr, KE1);

    conv_qk<<<(MTOT*DK)/256, 256>>>(qg, kg);
    conv_v <<<(MTOT*INTER)/256, 256>>>(0);

    bmma_gemm<2><<<dim3(SEQ/128, SEQ/128, BATCH), 256>>>(
        pqw, KES, (long)SEQ*KES, pqkT, SEQ, (long)KES*SEQ,
        pA, SEQ, (long)SEQ*SEQ,
        nullptr, 0, nullptr, 0, mask, KES);

    softmax_rows<<<MTOT, 256>>>(0);

    bmma_gemm<3><<<dim3(INTER/128, SEQ/128, BATCH), 256>>>(
        pP, KEA, (long)SEQ*KEA, pv, INTER, (long)KEA*INTER,
        nullptr, 0, 0,
        ppv, (long)SEQ*KEO, px, (long)SEQ*NCOL, nullptr, KEA);

    bmma_gemm<0><<<dim3(HID/128, MTOT/128, 1), 256>>>(
        ppv, KEO, 0, pWo, HID, 0, out, HID, 0,
        nullptr, 0, nullptr, 0, nullptr, KEO);
}